// round 2
// baseline (speedup 1.0000x reference)
#include <cuda_runtime.h>
#include <cuda_bf16.h>
#include <math.h>

// Problem dims
#define Bsz 2
#define Lseq 1024
#define Dm 1024
#define Ei 2048        // D_INNER
#define St 16          // D_STATE
#define Rr 64          // DT_RANK
#define XD 96          // DT_RANK + 2*D_STATE

// ---------------- scratch (static device globals; no allocation) -------------
__device__ __align__(256) float g_xz[(size_t)Bsz * Lseq * (2 * Ei)];   // 32MB: x|z
__device__ __align__(256) float g_u[(size_t)Bsz * Lseq * Ei];          // 16MB
__device__ __align__(256) float g_xdbl[(size_t)Bsz * Lseq * XD];       // 768KB
__device__ __align__(256) float g_delta[(size_t)Bsz * Lseq * Ei];      // 16MB
__device__ __align__(256) float g_outz[(size_t)Bsz * Lseq * Ei];       // 16MB

// ---------------- generic NT SGEMM: C[m,n] = sum_k A[m,k]*W[n,k] -------------
// BM=BN=128, BK=8, 256 threads, 8x8 per-thread micro-tile.
// M must be divisible by 128 (true for all calls: M=2048). N guarded. K%8==0.
// act: 0 = plain store, 1 = softplus(acc + bias[n])
__global__ __launch_bounds__(256) void gemm_nt(
    const float* __restrict__ A, int lda,
    const float* __restrict__ W, int ldw,
    float* __restrict__ C, int ldc,
    int M, int N, int K,
    const float* __restrict__ bias, int act)
{
    __shared__ float As[8][128];
    __shared__ float Ws[8][128];

    const int tid = threadIdx.x;
    const int tx = tid & 15;          // 0..15 (n groups)
    const int ty = tid >> 4;          // 0..15 (m groups)
    const int m0 = blockIdx.y * 128;
    const int n0 = blockIdx.x * 128;

    const int lr = tid >> 1;          // 0..127 row within tile
    const int lk = (tid & 1) * 4;     // 0 or 4

    float acc[8][8];
#pragma unroll
    for (int i = 0; i < 8; i++)
#pragma unroll
        for (int j = 0; j < 8; j++) acc[i][j] = 0.f;

    const float* Aload = A + (size_t)(m0 + lr) * lda + lk;
    const bool   wvalid = (n0 + lr) < N;
    const float* Wload = W + (size_t)(wvalid ? (n0 + lr) : 0) * ldw + lk;

    for (int k0 = 0; k0 < K; k0 += 8) {
        float4 av = *(const float4*)(Aload + k0);
        float4 wv = make_float4(0.f, 0.f, 0.f, 0.f);
        if (wvalid) wv = *(const float4*)(Wload + k0);

        __syncthreads();
        As[lk + 0][lr] = av.x; As[lk + 1][lr] = av.y;
        As[lk + 2][lr] = av.z; As[lk + 3][lr] = av.w;
        Ws[lk + 0][lr] = wv.x; Ws[lk + 1][lr] = wv.y;
        Ws[lk + 2][lr] = wv.z; Ws[lk + 3][lr] = wv.w;
        __syncthreads();

#pragma unroll
        for (int k = 0; k < 8; k++) {
            float4 a0 = *(const float4*)&As[k][ty * 8];
            float4 a1 = *(const float4*)&As[k][ty * 8 + 4];
            float4 b0 = *(const float4*)&Ws[k][tx * 8];
            float4 b1 = *(const float4*)&Ws[k][tx * 8 + 4];
            float ar[8] = {a0.x, a0.y, a0.z, a0.w, a1.x, a1.y, a1.z, a1.w};
            float br[8] = {b0.x, b0.y, b0.z, b0.w, b1.x, b1.y, b1.z, b1.w};
#pragma unroll
            for (int i = 0; i < 8; i++)
#pragma unroll
                for (int j = 0; j < 8; j++)
                    acc[i][j] = fmaf(ar[i], br[j], acc[i][j]);
        }
    }

#pragma unroll
    for (int i = 0; i < 8; i++) {
        int m = m0 + ty * 8 + i;
#pragma unroll
        for (int j = 0; j < 8; j++) {
            int n = n0 + tx * 8 + j;
            if (n < N) {
                float v = acc[i][j];
                if (act == 1) {
                    v += bias[n];
                    v = (v > 20.f) ? v : log1pf(__expf(v));
                }
                C[(size_t)m * ldc + n] = v;
            }
        }
    }
}

// ---------------- depthwise causal conv(4) + bias + SiLU ---------------------
// x = g_xz[..., 0:Ei] (row stride 2*Ei). u[b,l,e] = silu(sum_j x[b,l-3+j,e]*w[e,j]+b[e])
__global__ void conv_silu_kernel(const float* __restrict__ xz,
                                 const float* __restrict__ w4,
                                 const float* __restrict__ bias,
                                 float* __restrict__ u)
{
    int idx = blockIdx.x * blockDim.x + threadIdx.x;
    if (idx >= Bsz * Lseq * Ei) return;
    int e = idx & (Ei - 1);
    int l = (idx / Ei) & (Lseq - 1);
    int b = idx / (Ei * Lseq);

    float w0 = w4[e * 4 + 0], w1 = w4[e * 4 + 1], w2 = w4[e * 4 + 2], w3 = w4[e * 4 + 3];
    const float* xc = xz + ((size_t)b * Lseq) * (2 * Ei) + e;
    float acc = bias[e];
    if (l >= 3) acc = fmaf(xc[(size_t)(l - 3) * (2 * Ei)], w0, acc);
    if (l >= 2) acc = fmaf(xc[(size_t)(l - 2) * (2 * Ei)], w1, acc);
    if (l >= 1) acc = fmaf(xc[(size_t)(l - 1) * (2 * Ei)], w2, acc);
    acc = fmaf(xc[(size_t)l * (2 * Ei)], w3, acc);
    float sg = 1.f / (1.f + __expf(-acc));
    u[(size_t)idx] = acc * sg;
}

// ---------------- selective scan + gating -----------------------------------
// 2 channels per warp; lane = {sub=lane>>4 (channel), n=lane&15 (state)}.
// h_n recurrence in registers; y via 16-lane shfl reduction; fused +u*D and *silu(z).
__global__ __launch_bounds__(256) void scan_kernel(
    const float* __restrict__ xz,     // z at [...,(2048+d)] row stride 4096
    const float* __restrict__ u,
    const float* __restrict__ xdbl,   // [.,.,96]: dt(64) | B(16) | C(16)
    const float* __restrict__ delta,
    const float* __restrict__ A_log,  // (Ei, 16)
    const float* __restrict__ Dp,     // (Ei)
    float* __restrict__ outz)
{
    const int lane = threadIdx.x & 31;
    const int warp = (blockIdx.x * blockDim.x + threadIdx.x) >> 5;
    const int sub = lane >> 4;
    const int n = lane & 15;
    const int gch = warp * 2 + sub;          // 0..Bsz*Ei-1
    if (gch >= Bsz * Ei) return;
    const int b = gch / Ei;
    const int d = gch % Ei;

    const float An = -__expf(A_log[d * St + n]);
    const float Dd = Dp[d];

    const float* dptr = delta + (size_t)b * Lseq * Ei + d;
    const float* uptr = u + (size_t)b * Lseq * Ei + d;
    const float* xd   = xdbl + (size_t)b * Lseq * XD;
    const float* zptr = xz + (size_t)b * Lseq * (2 * Ei) + Ei + d;
    float* optr = outz + (size_t)b * Lseq * Ei + d;

    float h = 0.f;
    float dlt = dptr[0];
    float uu  = uptr[0];
    float Bv  = xd[Rr + n];
    float Cv  = xd[Rr + St + n];
    float zz  = zptr[0];
    float dA  = __expf(dlt * An);

    for (int l = 0; l < Lseq; l++) {
        const int ln = (l + 1 < Lseq) ? (l + 1) : l;
        // prefetch next step (off the h critical path)
        float dlt2 = dptr[(size_t)ln * Ei];
        float uu2  = uptr[(size_t)ln * Ei];
        float Bv2  = xd[(size_t)ln * XD + Rr + n];
        float Cv2  = xd[(size_t)ln * XD + Rr + St + n];
        float zz2  = zptr[(size_t)ln * (2 * Ei)];
        float dA2  = __expf(dlt2 * An);

        h = fmaf(dA, h, (dlt * uu) * Bv);
        float p = h * Cv;
        p += __shfl_xor_sync(0xffffffffu, p, 1);
        p += __shfl_xor_sync(0xffffffffu, p, 2);
        p += __shfl_xor_sync(0xffffffffu, p, 4);
        p += __shfl_xor_sync(0xffffffffu, p, 8);
        if (n == 0) {
            float y = p + uu * Dd;
            float sg = 1.f / (1.f + __expf(-zz));
            optr[(size_t)l * Ei] = y * (zz * sg);
        }
        dlt = dlt2; uu = uu2; Bv = Bv2; Cv = Cv2; zz = zz2; dA = dA2;
    }
}

// ---------------- launch ------------------------------------------------------
extern "C" void kernel_launch(void* const* d_in, const int* in_sizes, int n_in,
                              void* d_out, int out_size)
{
    const float* hidden    = (const float*)d_in[0];   // (B,L,Dm)
    const float* in_proj_w = (const float*)d_in[1];   // (2Ei, Dm)
    const float* conv1d_w  = (const float*)d_in[2];   // (Ei, 4)
    const float* conv1d_b  = (const float*)d_in[3];   // (Ei)
    const float* x_proj_w  = (const float*)d_in[4];   // (XD, Ei)
    const float* dt_proj_w = (const float*)d_in[5];   // (Ei, Rr)
    const float* dt_proj_b = (const float*)d_in[6];   // (Ei)
    const float* A_log     = (const float*)d_in[7];   // (Ei, St)
    const float* D_param   = (const float*)d_in[8];   // (Ei)
    const float* out_proj_w= (const float*)d_in[9];   // (Dm, Ei)
    float* out = (float*)d_out;

    float *xz, *u, *xdbl, *delta, *outz;
    cudaGetSymbolAddress((void**)&xz,    g_xz);
    cudaGetSymbolAddress((void**)&u,     g_u);
    cudaGetSymbolAddress((void**)&xdbl,  g_xdbl);
    cudaGetSymbolAddress((void**)&delta, g_delta);
    cudaGetSymbolAddress((void**)&outz,  g_outz);

    const int M = Bsz * Lseq;   // 2048

    // 1) in_proj: xz = hidden @ in_proj_w^T   (M x 4096, K=1024)
    {
        dim3 grid((2 * Ei) / 128, M / 128);
        gemm_nt<<<grid, 256>>>(hidden, Dm, in_proj_w, Dm, xz, 2 * Ei,
                               M, 2 * Ei, Dm, nullptr, 0);
    }
    // 2) conv + silu -> u
    {
        int total = Bsz * Lseq * Ei;
        conv_silu_kernel<<<(total + 255) / 256, 256>>>(xz, conv1d_w, conv1d_b, u);
    }
    // 3) x_proj: xdbl = u @ x_proj_w^T   (M x 96, K=2048)
    {
        dim3 grid((XD + 127) / 128, M / 128);
        gemm_nt<<<grid, 256>>>(u, Ei, x_proj_w, Ei, xdbl, XD,
                               M, XD, Ei, nullptr, 0);
    }
    // 4) delta = softplus(dt_low @ dt_proj_w^T + b)   (M x 2048, K=64, lda=96)
    {
        dim3 grid(Ei / 128, M / 128);
        gemm_nt<<<grid, 256>>>(xdbl, XD, dt_proj_w, Rr, delta, Ei,
                               M, Ei, Rr, dt_proj_b, 1);
    }
    // 5) selective scan + gating -> outz
    {
        int warps = (Bsz * Ei) / 2;            // 2048 warps
        int blocks = (warps * 32) / 256;       // 256 blocks
        scan_kernel<<<blocks, 256>>>(xz, u, xdbl, delta, A_log, D_param, outz);
    }
    // 6) out_proj: out = outz @ out_proj_w^T   (M x 1024, K=2048)
    {
        dim3 grid(Dm / 128, M / 128);
        gemm_nt<<<grid, 256>>>(outz, Ei, out_proj_w, Ei, out, Dm,
                               M, Dm, Ei, nullptr, 0);
    }
}

// round 7
// speedup vs baseline: 1.1892x; 1.1892x over previous
#include <cuda_runtime.h>
#include <cuda_bf16.h>
#include <math.h>

// Problem dims
#define Bsz 2
#define Lseq 1024
#define Dm 1024
#define Ei 2048        // D_INNER
#define St 16          // D_STATE
#define Rr 64          // DT_RANK
#define XD 96          // DT_RANK + 2*D_STATE

// ---------------- scratch (static device globals; no allocation) -------------
__device__ __align__(256) float g_xz[(size_t)Bsz * Lseq * (2 * Ei)];   // 32MB: x|z
__device__ __align__(256) float g_u[(size_t)Bsz * Lseq * Ei];          // 16MB
__device__ __align__(256) float g_xdbl[(size_t)Bsz * Lseq * XD];       // 768KB
__device__ __align__(256) float g_delta[(size_t)Bsz * Lseq * Ei];      // 16MB
__device__ __align__(256) float g_outz[(size_t)Bsz * Lseq * Ei];       // 16MB

// ---------------- packed f32x2 helpers (sm_103a FFMA2 path) ------------------
__device__ __forceinline__ unsigned long long splat2(float x) {
    unsigned long long r;
    unsigned int u = __float_as_uint(x);
    asm("mov.b64 %0, {%1, %1};" : "=l"(r) : "r"(u));
    return r;
}
__device__ __forceinline__ void ffma2(unsigned long long& d,
                                      unsigned long long a,
                                      unsigned long long b) {
    asm("fma.rn.f32x2 %0, %1, %2, %0;" : "+l"(d) : "l"(a), "l"(b));
}
__device__ __forceinline__ float lo32(unsigned long long v) {
    return __uint_as_float((unsigned int)v);
}
__device__ __forceinline__ float hi32(unsigned long long v) {
    return __uint_as_float((unsigned int)(v >> 32));
}

// ---------------- generic NT SGEMM: C[m,n] = sum_k A[m,k]*W[n,k] -------------
// BM=BN=128, BK=16, 256 threads, 8x8 per-thread micro-tile via f32x2 FMAs.
// Double-buffered smem, register prefetch, one __syncthreads per K-tile.
// M % 128 == 0 (always 2048 here). N guarded. K % 16 == 0.
// act: 0 = plain store, 1 = softplus(acc + bias[n])
__global__ __launch_bounds__(256, 2) void gemm_nt(
    const float* __restrict__ A, int lda,
    const float* __restrict__ W, int ldw,
    float* __restrict__ C, int ldc,
    int M, int N, int K,
    const float* __restrict__ bias, int act)
{
    __shared__ float As[2][16][128];
    __shared__ float Ws[2][16][128];

    const int tid = threadIdx.x;
    const int tx = tid & 15;          // 0..15 (n groups of 8)
    const int ty = tid >> 4;          // 0..15 (m groups of 8)
    const int m0 = blockIdx.y * 128;
    const int n0 = blockIdx.x * 128;

    const int lr = tid >> 1;          // 0..127 row within tile
    const int lk = (tid & 1) * 8;     // 0 or 8 (covers 8 cols via 2 float4)

    const float* Aload = A + (size_t)(m0 + lr) * lda + lk;
    const bool   wvalid = (n0 + lr) < N;
    const float* Wload = W + (size_t)(wvalid ? (n0 + lr) : 0) * ldw + lk;

    unsigned long long acc[4][8];     // [m-pair][n] ; lo=m even, hi=m odd
#pragma unroll
    for (int i = 0; i < 4; i++)
#pragma unroll
        for (int j = 0; j < 8; j++) acc[i][j] = 0ULL;

    const float4 f4z = make_float4(0.f, 0.f, 0.f, 0.f);

    // ---- preload tile 0 ----
    {
        float4 a0 = *(const float4*)(Aload);
        float4 a1 = *(const float4*)(Aload + 4);
        float4 w0 = f4z, w1 = f4z;
        if (wvalid) { w0 = *(const float4*)(Wload); w1 = *(const float4*)(Wload + 4); }
        As[0][lk + 0][lr] = a0.x; As[0][lk + 1][lr] = a0.y;
        As[0][lk + 2][lr] = a0.z; As[0][lk + 3][lr] = a0.w;
        As[0][lk + 4][lr] = a1.x; As[0][lk + 5][lr] = a1.y;
        As[0][lk + 6][lr] = a1.z; As[0][lk + 7][lr] = a1.w;
        Ws[0][lk + 0][lr] = w0.x; Ws[0][lk + 1][lr] = w0.y;
        Ws[0][lk + 2][lr] = w0.z; Ws[0][lk + 3][lr] = w0.w;
        Ws[0][lk + 4][lr] = w1.x; Ws[0][lk + 5][lr] = w1.y;
        Ws[0][lk + 6][lr] = w1.z; Ws[0][lk + 7][lr] = w1.w;
    }
    __syncthreads();

    int buf = 0;
    for (int k0 = 0; k0 < K; k0 += 16) {
        const bool more = (k0 + 16) < K;
        float4 na0, na1, nw0, nw1;
        if (more) {
            na0 = *(const float4*)(Aload + k0 + 16);
            na1 = *(const float4*)(Aload + k0 + 16 + 4);
            nw0 = f4z; nw1 = f4z;
            if (wvalid) {
                nw0 = *(const float4*)(Wload + k0 + 16);
                nw1 = *(const float4*)(Wload + k0 + 16 + 4);
            }
        }

#pragma unroll
        for (int k = 0; k < 16; k++) {
            ulonglong2 ap01 = *(const ulonglong2*)&As[buf][k][ty * 8];
            ulonglong2 ap23 = *(const ulonglong2*)&As[buf][k][ty * 8 + 4];
            float4 b0 = *(const float4*)&Ws[buf][k][tx * 8];
            float4 b1 = *(const float4*)&Ws[buf][k][tx * 8 + 4];
            unsigned long long ap[4] = {ap01.x, ap01.y, ap23.x, ap23.y};
            unsigned long long bp[8] = {
                splat2(b0.x), splat2(b0.y), splat2(b0.z), splat2(b0.w),
                splat2(b1.x), splat2(b1.y), splat2(b1.z), splat2(b1.w)};
#pragma unroll
            for (int i = 0; i < 4; i++)
#pragma unroll
                for (int j = 0; j < 8; j++)
                    ffma2(acc[i][j], ap[i], bp[j]);
        }

        if (more) {
            const int nb = buf ^ 1;
            As[nb][lk + 0][lr] = na0.x; As[nb][lk + 1][lr] = na0.y;
            As[nb][lk + 2][lr] = na0.z; As[nb][lk + 3][lr] = na0.w;
            As[nb][lk + 4][lr] = na1.x; As[nb][lk + 5][lr] = na1.y;
            As[nb][lk + 6][lr] = na1.z; As[nb][lk + 7][lr] = na1.w;
            Ws[nb][lk + 0][lr] = nw0.x; Ws[nb][lk + 1][lr] = nw0.y;
            Ws[nb][lk + 2][lr] = nw0.z; Ws[nb][lk + 3][lr] = nw0.w;
            Ws[nb][lk + 4][lr] = nw1.x; Ws[nb][lk + 5][lr] = nw1.y;
            Ws[nb][lk + 6][lr] = nw1.z; Ws[nb][lk + 7][lr] = nw1.w;
            __syncthreads();
            buf = nb;
        }
    }

    // ---- epilogue ----
    const int nbase = n0 + tx * 8;
    const bool nfull = (nbase + 7) < N;
#pragma unroll
    for (int i2 = 0; i2 < 4; i2++) {
#pragma unroll
        for (int h = 0; h < 2; h++) {
            const int m = m0 + ty * 8 + i2 * 2 + h;
            float v[8];
#pragma unroll
            for (int j = 0; j < 8; j++)
                v[j] = h ? hi32(acc[i2][j]) : lo32(acc[i2][j]);
            if (act == 1) {
#pragma unroll
                for (int j = 0; j < 8; j++) {
                    float t = v[j] + bias[nbase + j];
                    v[j] = (t > 20.f) ? t : log1pf(__expf(t));
                }
            }
            float* crow = C + (size_t)m * ldc + nbase;
            if (nfull) {
                *(float4*)(crow)     = make_float4(v[0], v[1], v[2], v[3]);
                *(float4*)(crow + 4) = make_float4(v[4], v[5], v[6], v[7]);
            } else {
#pragma unroll
                for (int j = 0; j < 8; j++)
                    if (nbase + j < N) crow[j] = v[j];
            }
        }
    }
}

// ---------------- depthwise causal conv(4) + bias + SiLU ---------------------
__global__ void conv_silu_kernel(const float* __restrict__ xz,
                                 const float* __restrict__ w4,
                                 const float* __restrict__ bias,
                                 float* __restrict__ u)
{
    int idx = blockIdx.x * blockDim.x + threadIdx.x;
    if (idx >= Bsz * Lseq * Ei) return;
    int e = idx & (Ei - 1);
    int l = (idx / Ei) & (Lseq - 1);
    int b = idx / (Ei * Lseq);

    float w0 = w4[e * 4 + 0], w1 = w4[e * 4 + 1], w2 = w4[e * 4 + 2], w3 = w4[e * 4 + 3];
    const float* xc = xz + ((size_t)b * Lseq) * (2 * Ei) + e;
    float acc = bias[e];
    if (l >= 3) acc = fmaf(xc[(size_t)(l - 3) * (2 * Ei)], w0, acc);
    if (l >= 2) acc = fmaf(xc[(size_t)(l - 2) * (2 * Ei)], w1, acc);
    if (l >= 1) acc = fmaf(xc[(size_t)(l - 1) * (2 * Ei)], w2, acc);
    acc = fmaf(xc[(size_t)l * (2 * Ei)], w3, acc);
    float sg = 1.f / (1.f + __expf(-acc));
    u[(size_t)idx] = acc * sg;
}

// ---------------- selective scan + gating -----------------------------------
__global__ __launch_bounds__(256) void scan_kernel(
    const float* __restrict__ xz,     // z at [...,(2048+d)] row stride 4096
    const float* __restrict__ u,
    const float* __restrict__ xdbl,   // [.,.,96]: dt(64) | B(16) | C(16)
    const float* __restrict__ delta,
    const float* __restrict__ A_log,  // (Ei, 16)
    const float* __restrict__ Dp,     // (Ei)
    float* __restrict__ outz)
{
    const int lane = threadIdx.x & 31;
    const int warp = (blockIdx.x * blockDim.x + threadIdx.x) >> 5;
    const int sub = lane >> 4;
    const int n = lane & 15;
    const int gch = warp * 2 + sub;          // 0..Bsz*Ei-1
    if (gch >= Bsz * Ei) return;
    const int b = gch / Ei;
    const int d = gch % Ei;

    const float An = -__expf(A_log[d * St + n]);
    const float Dd = Dp[d];

    const float* dptr = delta + (size_t)b * Lseq * Ei + d;
    const float* uptr = u + (size_t)b * Lseq * Ei + d;
    const float* xd   = xdbl + (size_t)b * Lseq * XD;
    const float* zptr = xz + (size_t)b * Lseq * (2 * Ei) + Ei + d;
    float* optr = outz + (size_t)b * Lseq * Ei + d;

    float h = 0.f;
    float dlt = dptr[0];
    float uu  = uptr[0];
    float Bv  = xd[Rr + n];
    float Cv  = xd[Rr + St + n];
    float zz  = zptr[0];
    float dA  = __expf(dlt * An);

    for (int l = 0; l < Lseq; l++) {
        const int ln = (l + 1 < Lseq) ? (l + 1) : l;
        // prefetch next step (off the h critical path)
        float dlt2 = dptr[(size_t)ln * Ei];
        float uu2  = uptr[(size_t)ln * Ei];
        float Bv2  = xd[(size_t)ln * XD + Rr + n];
        float Cv2  = xd[(size_t)ln * XD + Rr + St + n];
        float zz2  = zptr[(size_t)ln * (2 * Ei)];
        float dA2  = __expf(dlt2 * An);

        h = fmaf(dA, h, (dlt * uu) * Bv);
        float p = h * Cv;
        p += __shfl_xor_sync(0xffffffffu, p, 1);
        p += __shfl_xor_sync(0xffffffffu, p, 2);
        p += __shfl_xor_sync(0xffffffffu, p, 4);
        p += __shfl_xor_sync(0xffffffffu, p, 8);
        if (n == 0) {
            float y = p + uu * Dd;
            float sg = 1.f / (1.f + __expf(-zz));
            optr[(size_t)l * Ei] = y * (zz * sg);
        }
        dlt = dlt2; uu = uu2; Bv = Bv2; Cv = Cv2; zz = zz2; dA = dA2;
    }
}

// ---------------- launch ------------------------------------------------------
extern "C" void kernel_launch(void* const* d_in, const int* in_sizes, int n_in,
                              void* d_out, int out_size)
{
    const float* hidden    = (const float*)d_in[0];   // (B,L,Dm)
    const float* in_proj_w = (const float*)d_in[1];   // (2Ei, Dm)
    const float* conv1d_w  = (const float*)d_in[2];   // (Ei, 4)
    const float* conv1d_b  = (const float*)d_in[3];   // (Ei)
    const float* x_proj_w  = (const float*)d_in[4];   // (XD, Ei)
    const float* dt_proj_w = (const float*)d_in[5];   // (Ei, Rr)
    const float* dt_proj_b = (const float*)d_in[6];   // (Ei)
    const float* A_log     = (const float*)d_in[7];   // (Ei, St)
    const float* D_param   = (const float*)d_in[8];   // (Ei)
    const float* out_proj_w= (const float*)d_in[9];   // (Dm, Ei)
    float* out = (float*)d_out;

    float *xz, *u, *xdbl, *delta, *outz;
    cudaGetSymbolAddress((void**)&xz,    g_xz);
    cudaGetSymbolAddress((void**)&u,     g_u);
    cudaGetSymbolAddress((void**)&xdbl,  g_xdbl);
    cudaGetSymbolAddress((void**)&delta, g_delta);
    cudaGetSymbolAddress((void**)&outz,  g_outz);

    const int M = Bsz * Lseq;   // 2048

    // 1) in_proj: xz = hidden @ in_proj_w^T   (M x 4096, K=1024)
    {
        dim3 grid((2 * Ei) / 128, M / 128);
        gemm_nt<<<grid, 256>>>(hidden, Dm, in_proj_w, Dm, xz, 2 * Ei,
                               M, 2 * Ei, Dm, nullptr, 0);
    }
    // 2) conv + silu -> u
    {
        int total = Bsz * Lseq * Ei;
        conv_silu_kernel<<<(total + 255) / 256, 256>>>(xz, conv1d_w, conv1d_b, u);
    }
    // 3) x_proj: xdbl = u @ x_proj_w^T   (M x 96, K=2048)
    {
        dim3 grid((XD + 127) / 128, M / 128);
        gemm_nt<<<grid, 256>>>(u, Ei, x_proj_w, Ei, xdbl, XD,
                               M, XD, Ei, nullptr, 0);
    }
    // 4) delta = softplus(dt_low @ dt_proj_w^T + b)   (M x 2048, K=64, lda=96)
    {
        dim3 grid(Ei / 128, M / 128);
        gemm_nt<<<grid, 256>>>(xdbl, XD, dt_proj_w, Rr, delta, Ei,
                               M, Ei, Rr, dt_proj_b, 1);
    }
    // 5) selective scan + gating -> outz
    {
        int warps = (Bsz * Ei) / 2;            // 2048 warps
        int blocks = (warps * 32) / 256;       // 256 blocks
        scan_kernel<<<blocks, 256>>>(xz, u, xdbl, delta, A_log, D_param, outz);
    }
    // 6) out_proj: out = outz @ out_proj_w^T   (M x 1024, K=2048)
    {
        dim3 grid(Dm / 128, M / 128);
        gemm_nt<<<grid, 256>>>(outz, Ei, out_proj_w, Ei, out, Dm,
                               M, Dm, Ei, nullptr, 0);
    }
}